// round 4
// baseline (speedup 1.0000x reference)
#include <cuda_runtime.h>
#include <cuda_fp16.h>
#include <math.h>
#include <stdint.h>

typedef unsigned long long ull;

// ---------------- problem constants ----------------
#define HID  2048
#define R4   8192          // 4 * HID
#define TLEN 4096
#define IDIM 1024

// ---------------- recurrence kernel config ----------------
#define NBLK   128
#define NTHR   1024
#define HPB    16          // h indices per block (2048 / 128)
#define NCACHE 48          // rows of W_hh (fp16) cached in SMEM per block

// smem: 48 rows * 2048 halfs (196608 B) + h 2048 f + g 64 f + c 16 f
#define REC_SMEM_BYTES (NCACHE * HID * 2 + (HID + 64 + 16) * 4)

// ---------------- scratch (device globals; no allocation) ----------------
__device__ float    g_xg[(size_t)TLEN * R4];      // precomputed input gates, 128 MB
__device__ __half   g_whh[(size_t)R4 * HID];      // fp16 copy of W_hh, 32 MB
__device__ float    g_h[2][HID];                  // double-buffered hidden state
__device__ unsigned g_arrive[NBLK * 32];          // per-block arrival flags, 128B apart
__device__ volatile unsigned g_release;

// ---------------- init ----------------
__global__ void init_kernel() {
    if (threadIdx.x == 0) *(unsigned*)&g_release = 0u;
    for (int i = threadIdx.x; i < NBLK * 32; i += blockDim.x) g_arrive[i] = 0u;
    for (int i = threadIdx.x; i < HID; i += blockDim.x) g_h[0][i] = 0.0f;
}

// ---------------- W_hh fp32 -> fp16 ----------------
__global__ void prep_whh(const float* __restrict__ W_hh) {
    const size_t n2 = (size_t)R4 * HID / 2;
    const size_t stride = (size_t)gridDim.x * blockDim.x;
    for (size_t i = (size_t)blockIdx.x * blockDim.x + threadIdx.x; i < n2; i += stride) {
        float2 v = reinterpret_cast<const float2*>(W_hh)[i];
        reinterpret_cast<__half2*>(g_whh)[i] = __floats2half2_rn(v.x, v.y);
    }
}

// ---------------- packed f32x2 helpers ----------------
__device__ __forceinline__ void fma2_(ull& acc, ull a, ull b) {
    asm("fma.rn.f32x2 %0, %1, %2, %0;" : "+l"(acc) : "l"(a), "l"(b));
}
__device__ __forceinline__ ull h2_to_f2(unsigned h2) {
    ull r;
    asm("{\n\t"
        ".reg .b16 lo, hi;\n\t"
        ".reg .f32 flo, fhi;\n\t"
        "mov.b32 {lo, hi}, %1;\n\t"
        "cvt.f32.f16 flo, lo;\n\t"
        "cvt.f32.f16 fhi, hi;\n\t"
        "mov.b64 %0, {flo, fhi};\n\t"
        "}" : "=l"(r) : "r"(h2));
    return r;
}

// ---------------- xg GEMM: 128x128x16 tiles, 8x8 micro ----------------
#define GBM 128
#define GBN 128
#define GBK 16
#define GAP 132

__global__ __launch_bounds__(256) void xg_gemm(const float* __restrict__ x,
                                               const float* __restrict__ W_ih,
                                               const float* __restrict__ b_ih,
                                               const float* __restrict__ b_hh) {
    __shared__ float As[GBK * GAP];
    __shared__ float Bs[GBK * GAP];
    const int tid = threadIdx.x;
    const int tx = tid & 15;
    const int ty = tid >> 4;
    const int rt = blockIdx.x * GBN;
    const int tt = blockIdx.y * GBM;

    const int lr = tid >> 2;
    const int lc = (tid & 3) * 4;

    float acc[2][2][4][4];
    #pragma unroll
    for (int a = 0; a < 2; a++)
        #pragma unroll
        for (int b = 0; b < 2; b++)
            #pragma unroll
            for (int i = 0; i < 4; i++)
                #pragma unroll
                for (int j = 0; j < 4; j++) acc[a][b][i][j] = 0.f;

    for (int k0 = 0; k0 < IDIM; k0 += GBK) {
        float4 a0 = __ldg(reinterpret_cast<const float4*>(&x[(size_t)(tt + lr) * IDIM + k0 + lc]));
        float4 a1 = __ldg(reinterpret_cast<const float4*>(&x[(size_t)(tt + lr + 64) * IDIM + k0 + lc]));
        float4 w0 = __ldg(reinterpret_cast<const float4*>(&W_ih[(size_t)(rt + lr) * IDIM + k0 + lc]));
        float4 w1 = __ldg(reinterpret_cast<const float4*>(&W_ih[(size_t)(rt + lr + 64) * IDIM + k0 + lc]));

        As[(lc + 0) * GAP + lr] = a0.x; As[(lc + 1) * GAP + lr] = a0.y;
        As[(lc + 2) * GAP + lr] = a0.z; As[(lc + 3) * GAP + lr] = a0.w;
        As[(lc + 0) * GAP + lr + 64] = a1.x; As[(lc + 1) * GAP + lr + 64] = a1.y;
        As[(lc + 2) * GAP + lr + 64] = a1.z; As[(lc + 3) * GAP + lr + 64] = a1.w;

        Bs[(lc + 0) * GAP + lr] = w0.x; Bs[(lc + 1) * GAP + lr] = w0.y;
        Bs[(lc + 2) * GAP + lr] = w0.z; Bs[(lc + 3) * GAP + lr] = w0.w;
        Bs[(lc + 0) * GAP + lr + 64] = w1.x; Bs[(lc + 1) * GAP + lr + 64] = w1.y;
        Bs[(lc + 2) * GAP + lr + 64] = w1.z; Bs[(lc + 3) * GAP + lr + 64] = w1.w;

        __syncthreads();

        #pragma unroll
        for (int k = 0; k < GBK; k++) {
            float4 av0 = *reinterpret_cast<const float4*>(&As[k * GAP + ty * 4]);
            float4 av1 = *reinterpret_cast<const float4*>(&As[k * GAP + 64 + ty * 4]);
            float4 bv0 = *reinterpret_cast<const float4*>(&Bs[k * GAP + tx * 4]);
            float4 bv1 = *reinterpret_cast<const float4*>(&Bs[k * GAP + 64 + tx * 4]);
            float am[2][4] = {{av0.x, av0.y, av0.z, av0.w}, {av1.x, av1.y, av1.z, av1.w}};
            float bn[2][4] = {{bv0.x, bv0.y, bv0.z, bv0.w}, {bv1.x, bv1.y, bv1.z, bv1.w}};
            #pragma unroll
            for (int a = 0; a < 2; a++)
                #pragma unroll
                for (int i = 0; i < 4; i++)
                    #pragma unroll
                    for (int b = 0; b < 2; b++)
                        #pragma unroll
                        for (int j = 0; j < 4; j++)
                            acc[a][b][i][j] += am[a][i] * bn[b][j];
        }
        __syncthreads();
    }

    #pragma unroll
    for (int b = 0; b < 2; b++) {
        const int rbase = rt + b * 64 + tx * 4;
        float bias[4];
        #pragma unroll
        for (int j = 0; j < 4; j++) bias[j] = b_ih[rbase + j] + b_hh[rbase + j];
        #pragma unroll
        for (int a = 0; a < 2; a++) {
            #pragma unroll
            for (int i = 0; i < 4; i++) {
                const int t = tt + a * 64 + ty * 4 + i;
                float4 o;
                o.x = acc[a][b][i][0] + bias[0];
                o.y = acc[a][b][i][1] + bias[1];
                o.z = acc[a][b][i][2] + bias[2];
                o.w = acc[a][b][i][3] + bias[3];
                *reinterpret_cast<float4*>(&g_xg[(size_t)t * R4 + rbase]) = o;
            }
        }
    }
}

// ---------------- decentralized grid barrier ----------------
// Arrivals: per-block flag stores (parallel, no atomics).
// Block 0 threads 0..127 poll all flags; then block 0 publishes g_release.
// Other blocks spin on a plain volatile read of g_release.
__device__ __forceinline__ void grid_sync_(int bid, unsigned t) {
    __syncthreads();                      // all h(t) writes in this block done
    if (threadIdx.x == 0) {
        __threadfence();
        *(volatile unsigned*)&g_arrive[bid * 32] = t;
    }
    if (bid == 0) {
        if (threadIdx.x < NBLK) {
            while (*(volatile unsigned*)&g_arrive[threadIdx.x * 32] < t) { }
        }
        __syncthreads();                  // all 128 flags observed
        if (threadIdx.x == 0) {
            __threadfence();
            g_release = t;
        }
    } else {
        if (threadIdx.x == 0) {
            while (g_release < t) { }
            __threadfence();
        }
        __syncthreads();
    }
}

__device__ __forceinline__ float sigmoidf_(float v) { return 1.0f / (1.0f + expf(-v)); }

// ---------------- persistent LSTM recurrence (1024 thr, 2 rows/warp) ----------------
__global__ __launch_bounds__(NTHR, 1) void lstm_rec() {
    extern __shared__ float smem[];
    __half* wc   = reinterpret_cast<__half*>(smem);          // NCACHE * HID halfs
    float*  h_sh = smem + NCACHE * HID / 2;                  // HID floats
    float*  g_sh = h_sh + HID;                               // 64 gate pre-activations
    float*  c_sh = g_sh + 64;                                // 16 cell states

    const int tid   = threadIdx.x;
    const int bid   = blockIdx.x;
    const int hbase = bid * HPB;

    // stage local rows 0..47 (gates i,f,g for this slice) into SMEM as fp16
    for (int idx = tid; idx < NCACHE * HID / 8; idx += NTHR) {
        const int lr  = idx >> 8;               // local row (256 uint4 per row)
        const int col = (idx & 255) * 8;
        const int gate = lr >> 4;
        const int hl   = lr & 15;
        const size_t row = (size_t)(gate * HID + hbase + hl);
        reinterpret_cast<uint4*>(wc + (size_t)lr * HID)[col / 8] =
            __ldg(reinterpret_cast<const uint4*>(g_whh + row * HID + col));
    }
    if (tid < HPB) c_sh[tid] = 0.0f;

    const int warp = tid >> 5;
    const int lane = tid & 31;
    const int lr0  = warp * 2;                  // 2 rows per warp, same gate
    const int gate0 = lr0 >> 4;
    const int hl0   = lr0 & 15;
    const size_t rowg0 = (size_t)(gate0 * HID + hbase + hl0);   // global row (pair contiguous)
    const __half* sm_base = wc + (size_t)lr0 * HID;
    const __half* gl_base = g_whh + rowg0 * HID;
    const bool use_sm = (lr0 + 1 < NCACHE);

    for (int t = 0; t < TLEN; t++) {
        // prefetch xg pair (h-independent; hides DRAM latency behind barrier)
        float2 xgv = make_float2(0.f, 0.f);
        if (lane == 0)
            xgv = __ldg(reinterpret_cast<const float2*>(g_xg + (size_t)t * R4 + rowg0));

        grid_sync_(bid, (unsigned)(t + 1));      // h(t) from all blocks now visible

        const float* hsrc = g_h[t & 1];
        *reinterpret_cast<float2*>(h_sh + tid * 2) =
            *reinterpret_cast<const float2*>(hsrc + tid * 2);
        __syncthreads();

        // 2-row dot: fp16 weights, f32x2 accumulation
        ull acc00 = 0ull, acc01 = 0ull, acc10 = 0ull, acc11 = 0ull;
        #pragma unroll
        for (int ch = 0; ch < 8; ch++) {
            const int off = ch * 256 + lane * 8;   // column index (halves == floats)
            const ulonglong2* hp = reinterpret_cast<const ulonglong2*>(h_sh + off);
            ulonglong2 hA = hp[0];                 // h[off..off+3]
            ulonglong2 hB = hp[1];                 // h[off+4..off+7]
            uint4 w0, w1;
            if (use_sm) {
                w0 = *reinterpret_cast<const uint4*>(sm_base + off);
                w1 = *reinterpret_cast<const uint4*>(sm_base + HID + off);
            } else {
                w0 = __ldg(reinterpret_cast<const uint4*>(gl_base + off));
                w1 = __ldg(reinterpret_cast<const uint4*>(gl_base + HID + off));
            }
            fma2_(acc00, h2_to_f2(w0.x), hA.x);
            fma2_(acc01, h2_to_f2(w0.y), hA.y);
            fma2_(acc00, h2_to_f2(w0.z), hB.x);
            fma2_(acc01, h2_to_f2(w0.w), hB.y);
            fma2_(acc10, h2_to_f2(w1.x), hA.x);
            fma2_(acc11, h2_to_f2(w1.y), hA.y);
            fma2_(acc10, h2_to_f2(w1.z), hB.x);
            fma2_(acc11, h2_to_f2(w1.w), hB.y);
        }
        float a0, a1;
        {
            ull s0, s1;
            asm("add.rn.f32x2 %0, %1, %2;" : "=l"(s0) : "l"(acc00), "l"(acc01));
            asm("add.rn.f32x2 %0, %1, %2;" : "=l"(s1) : "l"(acc10), "l"(acc11));
            float l0, h0, l1, h1;
            asm("mov.b64 {%0, %1}, %2;" : "=f"(l0), "=f"(h0) : "l"(s0));
            asm("mov.b64 {%0, %1}, %2;" : "=f"(l1), "=f"(h1) : "l"(s1));
            a0 = l0 + h0; a1 = l1 + h1;
        }
        #pragma unroll
        for (int off = 16; off; off >>= 1) {
            a0 += __shfl_xor_sync(0xFFFFFFFFu, a0, off);
            a1 += __shfl_xor_sync(0xFFFFFFFFu, a1, off);
        }
        if (lane == 0) {
            g_sh[lr0 + 0] = a0 + xgv.x;
            g_sh[lr0 + 1] = a1 + xgv.y;
        }
        __syncthreads();

        if (tid < HPB) {
            const float iv = sigmoidf_(g_sh[tid]);
            const float fv = sigmoidf_(g_sh[16 + tid]);
            const float gv = tanhf(g_sh[32 + tid]);
            const float ov = sigmoidf_(g_sh[48 + tid]);
            const float c  = fv * c_sh[tid] + iv * gv;
            c_sh[tid] = c;
            g_h[(t + 1) & 1][hbase + tid] = ov * tanhf(c);
        }
    }
}

// ---------------- output layer ----------------
__global__ void out_kernel(const float* __restrict__ W_out,
                           const float* __restrict__ b_out,
                           float* __restrict__ out) {
    __shared__ float red[8];
    const int tid = threadIdx.x;   // 256 threads
    const float* hfin = g_h[0];    // TLEN even -> final h in buffer 0
    float s = 0.f;
    for (int j = tid; j < HID; j += 256) s += hfin[j] * W_out[j];
    #pragma unroll
    for (int off = 16; off; off >>= 1) s += __shfl_xor_sync(0xFFFFFFFFu, s, off);
    if ((tid & 31) == 0) red[tid >> 5] = s;
    __syncthreads();
    if (tid < 8) {
        float v = red[tid];
        #pragma unroll
        for (int off = 4; off; off >>= 1) v += __shfl_xor_sync(0xFFu, v, off);
        if (tid == 0) out[0] = v + b_out[0];
    }
}

// ---------------- launch ----------------
extern "C" void kernel_launch(void* const* d_in, const int* in_sizes, int n_in,
                              void* d_out, int out_size) {
    const float* x     = (const float*)d_in[0];
    const float* W_ih  = (const float*)d_in[1];
    const float* W_hh  = (const float*)d_in[2];
    const float* b_ih  = (const float*)d_in[3];
    const float* b_hh  = (const float*)d_in[4];
    const float* W_out = (const float*)d_in[5];
    const float* b_out = (const float*)d_in[6];
    float* out = (float*)d_out;

    init_kernel<<<1, 256>>>();
    prep_whh<<<2048, 256>>>(W_hh);

    dim3 ggrid(R4 / GBN, TLEN / GBM);
    xg_gemm<<<ggrid, 256>>>(x, W_ih, b_ih, b_hh);

    cudaFuncSetAttribute(lstm_rec, cudaFuncAttributeMaxDynamicSharedMemorySize, REC_SMEM_BYTES);
    lstm_rec<<<NBLK, NTHR, REC_SMEM_BYTES>>>();

    out_kernel<<<1, 256>>>(W_out, b_out, out);
}

// round 5
// speedup vs baseline: 1.2922x; 1.2922x over previous
#include <cuda_runtime.h>
#include <cuda_fp16.h>
#include <math.h>
#include <stdint.h>

typedef unsigned long long ull;

// ---------------- problem constants ----------------
#define HID  2048
#define R4   8192          // 4 * HID
#define TLEN 4096
#define IDIM 1024

// ---------------- recurrence kernel config ----------------
#define NBLK   128
#define NTHR   512
#define HPB    16          // h indices per block (2048 / 128)
#define NCACHE 48          // rows of W_hh (fp16) cached in SMEM per block

// smem: 48 rows * 2048 halfs (196608 B) + h 2048 f + g 64 f + c 16 f
#define REC_SMEM_BYTES (NCACHE * HID * 2 + (HID + 64 + 16) * 4)

// ---------------- scratch (device globals; no allocation) ----------------
__device__ float    g_xg[(size_t)TLEN * R4];      // precomputed input gates, 128 MB
__device__ __half   g_whh[(size_t)R4 * HID];      // fp16 copy of W_hh, 32 MB
__device__ float    g_h[2][HID];                  // double-buffered hidden state
__device__ unsigned g_flag[NBLK * 32];            // per-block publish flags, 128B apart

// ---------------- init ----------------
__global__ void init_kernel() {
    for (int i = threadIdx.x; i < NBLK * 32; i += blockDim.x) g_flag[i] = 0u;
    for (int i = threadIdx.x; i < HID; i += blockDim.x) g_h[0][i] = 0.0f;
}

// ---------------- W_hh fp32 -> fp16 ----------------
__global__ void prep_whh(const float* __restrict__ W_hh) {
    const size_t n2 = (size_t)R4 * HID / 2;
    const size_t stride = (size_t)gridDim.x * blockDim.x;
    for (size_t i = (size_t)blockIdx.x * blockDim.x + threadIdx.x; i < n2; i += stride) {
        float2 v = reinterpret_cast<const float2*>(W_hh)[i];
        reinterpret_cast<__half2*>(g_whh)[i] = __floats2half2_rn(v.x, v.y);
    }
}

// ---------------- packed f32x2 helpers ----------------
__device__ __forceinline__ void fma2_(ull& acc, ull a, ull b) {
    asm("fma.rn.f32x2 %0, %1, %2, %0;" : "+l"(acc) : "l"(a), "l"(b));
}
__device__ __forceinline__ ull h2_to_f2(unsigned h2) {
    ull r;
    asm("{\n\t"
        ".reg .b16 lo, hi;\n\t"
        ".reg .f32 flo, fhi;\n\t"
        "mov.b32 {lo, hi}, %1;\n\t"
        "cvt.f32.f16 flo, lo;\n\t"
        "cvt.f32.f16 fhi, hi;\n\t"
        "mov.b64 %0, {flo, fhi};\n\t"
        "}" : "=l"(r) : "r"(h2));
    return r;
}

// ---------------- xg GEMM: 128x128x16 tiles, 8x8 micro ----------------
#define GBM 128
#define GBN 128
#define GBK 16
#define GAP 132

__global__ __launch_bounds__(256) void xg_gemm(const float* __restrict__ x,
                                               const float* __restrict__ W_ih,
                                               const float* __restrict__ b_ih,
                                               const float* __restrict__ b_hh) {
    __shared__ float As[GBK * GAP];
    __shared__ float Bs[GBK * GAP];
    const int tid = threadIdx.x;
    const int tx = tid & 15;
    const int ty = tid >> 4;
    const int rt = blockIdx.x * GBN;
    const int tt = blockIdx.y * GBM;

    const int lr = tid >> 2;
    const int lc = (tid & 3) * 4;

    float acc[2][2][4][4];
    #pragma unroll
    for (int a = 0; a < 2; a++)
        #pragma unroll
        for (int b = 0; b < 2; b++)
            #pragma unroll
            for (int i = 0; i < 4; i++)
                #pragma unroll
                for (int j = 0; j < 4; j++) acc[a][b][i][j] = 0.f;

    for (int k0 = 0; k0 < IDIM; k0 += GBK) {
        float4 a0 = __ldg(reinterpret_cast<const float4*>(&x[(size_t)(tt + lr) * IDIM + k0 + lc]));
        float4 a1 = __ldg(reinterpret_cast<const float4*>(&x[(size_t)(tt + lr + 64) * IDIM + k0 + lc]));
        float4 w0 = __ldg(reinterpret_cast<const float4*>(&W_ih[(size_t)(rt + lr) * IDIM + k0 + lc]));
        float4 w1 = __ldg(reinterpret_cast<const float4*>(&W_ih[(size_t)(rt + lr + 64) * IDIM + k0 + lc]));

        As[(lc + 0) * GAP + lr] = a0.x; As[(lc + 1) * GAP + lr] = a0.y;
        As[(lc + 2) * GAP + lr] = a0.z; As[(lc + 3) * GAP + lr] = a0.w;
        As[(lc + 0) * GAP + lr + 64] = a1.x; As[(lc + 1) * GAP + lr + 64] = a1.y;
        As[(lc + 2) * GAP + lr + 64] = a1.z; As[(lc + 3) * GAP + lr + 64] = a1.w;

        Bs[(lc + 0) * GAP + lr] = w0.x; Bs[(lc + 1) * GAP + lr] = w0.y;
        Bs[(lc + 2) * GAP + lr] = w0.z; Bs[(lc + 3) * GAP + lr] = w0.w;
        Bs[(lc + 0) * GAP + lr + 64] = w1.x; Bs[(lc + 1) * GAP + lr + 64] = w1.y;
        Bs[(lc + 2) * GAP + lr + 64] = w1.z; Bs[(lc + 3) * GAP + lr + 64] = w1.w;

        __syncthreads();

        #pragma unroll
        for (int k = 0; k < GBK; k++) {
            float4 av0 = *reinterpret_cast<const float4*>(&As[k * GAP + ty * 4]);
            float4 av1 = *reinterpret_cast<const float4*>(&As[k * GAP + 64 + ty * 4]);
            float4 bv0 = *reinterpret_cast<const float4*>(&Bs[k * GAP + tx * 4]);
            float4 bv1 = *reinterpret_cast<const float4*>(&Bs[k * GAP + 64 + tx * 4]);
            float am[2][4] = {{av0.x, av0.y, av0.z, av0.w}, {av1.x, av1.y, av1.z, av1.w}};
            float bn[2][4] = {{bv0.x, bv0.y, bv0.z, bv0.w}, {bv1.x, bv1.y, bv1.z, bv1.w}};
            #pragma unroll
            for (int a = 0; a < 2; a++)
                #pragma unroll
                for (int i = 0; i < 4; i++)
                    #pragma unroll
                    for (int b = 0; b < 2; b++)
                        #pragma unroll
                        for (int j = 0; j < 4; j++)
                            acc[a][b][i][j] += am[a][i] * bn[b][j];
        }
        __syncthreads();
    }

    #pragma unroll
    for (int b = 0; b < 2; b++) {
        const int rbase = rt + b * 64 + tx * 4;
        float bias[4];
        #pragma unroll
        for (int j = 0; j < 4; j++) bias[j] = b_ih[rbase + j] + b_hh[rbase + j];
        #pragma unroll
        for (int a = 0; a < 2; a++) {
            #pragma unroll
            for (int i = 0; i < 4; i++) {
                const int t = tt + a * 64 + ty * 4 + i;
                float4 o;
                o.x = acc[a][b][i][0] + bias[0];
                o.y = acc[a][b][i][1] + bias[1];
                o.z = acc[a][b][i][2] + bias[2];
                o.w = acc[a][b][i][3] + bias[3];
                *reinterpret_cast<float4*>(&g_xg[(size_t)t * R4 + rbase]) = o;
            }
        }
    }
}

__device__ __forceinline__ float sigmoidf_(float v) { return 1.0f / (1.0f + expf(-v)); }

// ---------------- 4-row dot (fp16 weights, f32x2 accumulation) ----------------
template<bool SM>
__device__ __forceinline__ void dot4rows(const __half* __restrict__ base,
                                         const float* __restrict__ h_sh,
                                         int lane, float out[4]) {
    ull acc[4][2] = {{0ull,0ull},{0ull,0ull},{0ull,0ull},{0ull,0ull}};
    #pragma unroll
    for (int pass = 0; pass < 2; pass++) {
        ull hh[4][4];
        #pragma unroll
        for (int c = 0; c < 4; c++) {
            const ulonglong2* hp =
                reinterpret_cast<const ulonglong2*>(h_sh + pass * 1024 + c * 256 + lane * 8);
            ulonglong2 v0 = hp[0];
            ulonglong2 v1 = hp[1];
            hh[c][0] = v0.x; hh[c][1] = v0.y; hh[c][2] = v1.x; hh[c][3] = v1.y;
        }
        #pragma unroll
        for (int r = 0; r < 4; r++) {
            #pragma unroll
            for (int c = 0; c < 4; c++) {
                const uint4* wp = reinterpret_cast<const uint4*>(
                    base + r * HID + pass * 1024 + c * 256 + lane * 8);
                uint4 w = SM ? *wp : __ldg(wp);
                fma2_(acc[r][0], h2_to_f2(w.x), hh[c][0]);
                fma2_(acc[r][1], h2_to_f2(w.y), hh[c][1]);
                fma2_(acc[r][0], h2_to_f2(w.z), hh[c][2]);
                fma2_(acc[r][1], h2_to_f2(w.w), hh[c][3]);
            }
        }
    }
    #pragma unroll
    for (int r = 0; r < 4; r++) {
        ull s;
        asm("add.rn.f32x2 %0, %1, %2;" : "=l"(s) : "l"(acc[r][0]), "l"(acc[r][1]));
        float lo, hi;
        asm("mov.b64 {%0, %1}, %2;" : "=f"(lo), "=f"(hi) : "l"(s));
        out[r] = lo + hi;
    }
}

// ---------------- persistent LSTM recurrence ----------------
__global__ __launch_bounds__(NTHR, 1) void lstm_rec() {
    extern __shared__ float smem[];
    __half* wc   = reinterpret_cast<__half*>(smem);          // NCACHE * HID halfs
    float*  h_sh = smem + NCACHE * HID / 2;                  // HID floats
    float*  g_sh = h_sh + HID;                               // 64 gate pre-activations
    float*  c_sh = g_sh + 64;                                // 16 cell states

    const int tid   = threadIdx.x;
    const int bid   = blockIdx.x;
    const int hbase = bid * HPB;

    // stage NCACHE rows into SMEM as fp16
    for (int idx = tid; idx < NCACHE * HID / 8; idx += NTHR) {
        const int lr  = idx >> 8;
        const int col = (idx & 255) * 8;
        const int gate = lr >> 4;
        const int hl   = lr & 15;
        const size_t row = (size_t)(gate * HID + hbase + hl);
        reinterpret_cast<uint4*>(wc + (size_t)lr * HID)[col / 8] =
            __ldg(reinterpret_cast<const uint4*>(g_whh + row * HID + col));
    }
    if (tid < HPB) c_sh[tid] = 0.0f;

    const int warp = tid >> 5;
    const int lane = tid & 31;
    const int lr0  = warp * 4;
    const int gate0 = lr0 >> 4;
    const int hl0   = lr0 & 15;
    const size_t rowg0 = (size_t)(gate0 * HID + hbase + hl0);
    const __half* sm_base = wc + (size_t)lr0 * HID;
    const __half* gl_base = g_whh + rowg0 * HID;
    const bool use_sm = (lr0 + 3 < NCACHE);

    for (int t = 0; t < TLEN; t++) {
        // publish h(t) (written at end of previous iteration; end-sync already done)
        if (t > 0 && tid == 0) {
            __threadfence();
            *(volatile unsigned*)&g_flag[bid * 32] = (unsigned)t;
        }

        // prefetch xg row (h-independent; overlaps the wait)
        float4 xgv = make_float4(0.f, 0.f, 0.f, 0.f);
        if (lane == 0)
            xgv = __ldg(reinterpret_cast<const float4*>(g_xg + (size_t)t * R4 + rowg0));

        // one-hop wait: 128 threads poll all 128 producer flags in parallel
        if (tid < NBLK) {
            while (*(volatile unsigned*)&g_flag[tid * 32] < (unsigned)t) { }
            __threadfence();
        }
        __syncthreads();

        const float* hsrc = g_h[t & 1];
        *reinterpret_cast<float4*>(h_sh + tid * 4) =
            *reinterpret_cast<const float4*>(hsrc + tid * 4);
        __syncthreads();

        float a[4];
        if (use_sm) dot4rows<true >(sm_base, h_sh, lane, a);
        else        dot4rows<false>(gl_base, h_sh, lane, a);

        #pragma unroll
        for (int off = 16; off; off >>= 1) {
            a[0] += __shfl_xor_sync(0xFFFFFFFFu, a[0], off);
            a[1] += __shfl_xor_sync(0xFFFFFFFFu, a[1], off);
            a[2] += __shfl_xor_sync(0xFFFFFFFFu, a[2], off);
            a[3] += __shfl_xor_sync(0xFFFFFFFFu, a[3], off);
        }
        if (lane == 0) {
            g_sh[lr0 + 0] = a[0] + xgv.x;
            g_sh[lr0 + 1] = a[1] + xgv.y;
            g_sh[lr0 + 2] = a[2] + xgv.z;
            g_sh[lr0 + 3] = a[3] + xgv.w;
        }
        __syncthreads();

        if (tid < HPB) {
            const float iv = sigmoidf_(g_sh[tid]);
            const float fv = sigmoidf_(g_sh[16 + tid]);
            const float gv = tanhf(g_sh[32 + tid]);
            const float ov = sigmoidf_(g_sh[48 + tid]);
            const float c  = fv * c_sh[tid] + iv * gv;
            c_sh[tid] = c;
            g_h[(t + 1) & 1][hbase + tid] = ov * tanhf(c);
        }
        __syncthreads();   // h(t+1) writes complete block-wide before next publish
    }
}

// ---------------- output layer ----------------
__global__ void out_kernel(const float* __restrict__ W_out,
                           const float* __restrict__ b_out,
                           float* __restrict__ out) {
    __shared__ float red[8];
    const int tid = threadIdx.x;   // 256 threads
    const float* hfin = g_h[0];    // TLEN even -> final h in buffer 0
    float s = 0.f;
    for (int j = tid; j < HID; j += 256) s += hfin[j] * W_out[j];
    #pragma unroll
    for (int off = 16; off; off >>= 1) s += __shfl_xor_sync(0xFFFFFFFFu, s, off);
    if ((tid & 31) == 0) red[tid >> 5] = s;
    __syncthreads();
    if (tid < 8) {
        float v = red[tid];
        #pragma unroll
        for (int off = 4; off; off >>= 1) v += __shfl_xor_sync(0xFFu, v, off);
        if (tid == 0) out[0] = v + b_out[0];
    }
}

// ---------------- launch ----------------
extern "C" void kernel_launch(void* const* d_in, const int* in_sizes, int n_in,
                              void* d_out, int out_size) {
    const float* x     = (const float*)d_in[0];
    const float* W_ih  = (const float*)d_in[1];
    const float* W_hh  = (const float*)d_in[2];
    const float* b_ih  = (const float*)d_in[3];
    const float* b_hh  = (const float*)d_in[4];
    const float* W_out = (const float*)d_in[5];
    const float* b_out = (const float*)d_in[6];
    float* out = (float*)d_out;

    init_kernel<<<1, 256>>>();
    prep_whh<<<2048, 256>>>(W_hh);

    dim3 ggrid(R4 / GBN, TLEN / GBM);
    xg_gemm<<<ggrid, 256>>>(x, W_ih, b_ih, b_hh);

    cudaFuncSetAttribute(lstm_rec, cudaFuncAttributeMaxDynamicSharedMemorySize, REC_SMEM_BYTES);
    lstm_rec<<<NBLK, NTHR, REC_SMEM_BYTES>>>();

    out_kernel<<<1, 256>>>(W_out, b_out, out);
}

// round 6
// speedup vs baseline: 1.3489x; 1.0439x over previous
#include <cuda_runtime.h>
#include <cuda_fp16.h>
#include <math.h>
#include <stdint.h>

typedef unsigned long long ull;

// ---------------- problem constants ----------------
#define HID  2048
#define R4   8192          // 4 * HID
#define TLEN 4096
#define IDIM 1024

// ---------------- recurrence kernel config ----------------
#define NBLK   128
#define NTHR   512
#define HPB    16          // h indices per block (2048 / 128)
#define NCACHE 48          // rows of W_hh (fp16) cached in SMEM per block

// smem: 48 rows * 2048 halfs + h 2048 halfs + g 64 f + c 16 f
#define REC_SMEM_BYTES (NCACHE * HID * 2 + HID * 2 + (64 + 16) * 4)

// ---------------- scratch (device globals; no allocation) ----------------
__device__ float    g_xg[(size_t)TLEN * R4];      // precomputed input gates, 128 MB
__device__ __half   g_whh[(size_t)R4 * HID];      // fp16 copy of W_hh, 32 MB

// message line: 16 h values (fp32) + tag, one 128B line per block, double buffered
struct alignas(128) Msg { float h[16]; unsigned tag; unsigned pad[15]; };
__device__ Msg g_msg[2][NBLK];

// ---------------- init ----------------
__global__ void init_kernel() {
    unsigned* p = reinterpret_cast<unsigned*>(g_msg);
    for (int i = threadIdx.x; i < 2 * NBLK * 32; i += blockDim.x) p[i] = 0u;
}

// ---------------- W_hh fp32 -> fp16 ----------------
__global__ void prep_whh(const float* __restrict__ W_hh) {
    const size_t n2 = (size_t)R4 * HID / 2;
    const size_t stride = (size_t)gridDim.x * blockDim.x;
    for (size_t i = (size_t)blockIdx.x * blockDim.x + threadIdx.x; i < n2; i += stride) {
        float2 v = reinterpret_cast<const float2*>(W_hh)[i];
        reinterpret_cast<__half2*>(g_whh)[i] = __floats2half2_rn(v.x, v.y);
    }
}

// ---------------- xg GEMM: 128x128x16 tiles, 8x8 micro (unchanged, proven) ----------------
#define GBM 128
#define GBN 128
#define GBK 16
#define GAP 132

__global__ __launch_bounds__(256) void xg_gemm(const float* __restrict__ x,
                                               const float* __restrict__ W_ih,
                                               const float* __restrict__ b_ih,
                                               const float* __restrict__ b_hh) {
    __shared__ float As[GBK * GAP];
    __shared__ float Bs[GBK * GAP];
    const int tid = threadIdx.x;
    const int tx = tid & 15;
    const int ty = tid >> 4;
    const int rt = blockIdx.x * GBN;
    const int tt = blockIdx.y * GBM;

    const int lr = tid >> 2;
    const int lc = (tid & 3) * 4;

    float acc[2][2][4][4];
    #pragma unroll
    for (int a = 0; a < 2; a++)
        #pragma unroll
        for (int b = 0; b < 2; b++)
            #pragma unroll
            for (int i = 0; i < 4; i++)
                #pragma unroll
                for (int j = 0; j < 4; j++) acc[a][b][i][j] = 0.f;

    for (int k0 = 0; k0 < IDIM; k0 += GBK) {
        float4 a0 = __ldg(reinterpret_cast<const float4*>(&x[(size_t)(tt + lr) * IDIM + k0 + lc]));
        float4 a1 = __ldg(reinterpret_cast<const float4*>(&x[(size_t)(tt + lr + 64) * IDIM + k0 + lc]));
        float4 w0 = __ldg(reinterpret_cast<const float4*>(&W_ih[(size_t)(rt + lr) * IDIM + k0 + lc]));
        float4 w1 = __ldg(reinterpret_cast<const float4*>(&W_ih[(size_t)(rt + lr + 64) * IDIM + k0 + lc]));

        As[(lc + 0) * GAP + lr] = a0.x; As[(lc + 1) * GAP + lr] = a0.y;
        As[(lc + 2) * GAP + lr] = a0.z; As[(lc + 3) * GAP + lr] = a0.w;
        As[(lc + 0) * GAP + lr + 64] = a1.x; As[(lc + 1) * GAP + lr + 64] = a1.y;
        As[(lc + 2) * GAP + lr + 64] = a1.z; As[(lc + 3) * GAP + lr + 64] = a1.w;

        Bs[(lc + 0) * GAP + lr] = w0.x; Bs[(lc + 1) * GAP + lr] = w0.y;
        Bs[(lc + 2) * GAP + lr] = w0.z; Bs[(lc + 3) * GAP + lr] = w0.w;
        Bs[(lc + 0) * GAP + lr + 64] = w1.x; Bs[(lc + 1) * GAP + lr + 64] = w1.y;
        Bs[(lc + 2) * GAP + lr + 64] = w1.z; Bs[(lc + 3) * GAP + lr + 64] = w1.w;

        __syncthreads();

        #pragma unroll
        for (int k = 0; k < GBK; k++) {
            float4 av0 = *reinterpret_cast<const float4*>(&As[k * GAP + ty * 4]);
            float4 av1 = *reinterpret_cast<const float4*>(&As[k * GAP + 64 + ty * 4]);
            float4 bv0 = *reinterpret_cast<const float4*>(&Bs[k * GAP + tx * 4]);
            float4 bv1 = *reinterpret_cast<const float4*>(&Bs[k * GAP + 64 + tx * 4]);
            float am[2][4] = {{av0.x, av0.y, av0.z, av0.w}, {av1.x, av1.y, av1.z, av1.w}};
            float bn[2][4] = {{bv0.x, bv0.y, bv0.z, bv0.w}, {bv1.x, bv1.y, bv1.z, bv1.w}};
            #pragma unroll
            for (int a = 0; a < 2; a++)
                #pragma unroll
                for (int i = 0; i < 4; i++)
                    #pragma unroll
                    for (int b = 0; b < 2; b++)
                        #pragma unroll
                        for (int j = 0; j < 4; j++)
                            acc[a][b][i][j] += am[a][i] * bn[b][j];
        }
        __syncthreads();
    }

    #pragma unroll
    for (int b = 0; b < 2; b++) {
        const int rbase = rt + b * 64 + tx * 4;
        float bias[4];
        #pragma unroll
        for (int j = 0; j < 4; j++) bias[j] = b_ih[rbase + j] + b_hh[rbase + j];
        #pragma unroll
        for (int a = 0; a < 2; a++) {
            #pragma unroll
            for (int i = 0; i < 4; i++) {
                const int t = tt + a * 64 + ty * 4 + i;
                float4 o;
                o.x = acc[a][b][i][0] + bias[0];
                o.y = acc[a][b][i][1] + bias[1];
                o.z = acc[a][b][i][2] + bias[2];
                o.w = acc[a][b][i][3] + bias[3];
                *reinterpret_cast<float4*>(&g_xg[(size_t)t * R4 + rbase]) = o;
            }
        }
    }
}

__device__ __forceinline__ float sigmoidf_(float v) { return 1.0f / (1.0f + expf(-v)); }
__device__ __forceinline__ __half2 u2h_(unsigned u) { return *reinterpret_cast<__half2*>(&u); }

// ---------------- 4-row dot: HFMA2 chunks (8 elems) -> f32x2 accumulators ----------------
template<bool SM>
__device__ __forceinline__ void dot4(const __half* __restrict__ base,
                                     const __half* __restrict__ h2sh,
                                     int lane, float out[4]) {
    ull acc[4] = {0ull, 0ull, 0ull, 0ull};
    #pragma unroll
    for (int ch = 0; ch < 8; ch++) {
        const int off = ch * 256 + lane * 8;   // half index
        uint4 hv = *reinterpret_cast<const uint4*>(h2sh + off);
        #pragma unroll
        for (int r = 0; r < 4; r++) {
            uint4 w = SM ? *reinterpret_cast<const uint4*>(base + r * HID + off)
                         : __ldg(reinterpret_cast<const uint4*>(base + r * HID + off));
            __half2 s = __hmul2(u2h_(w.x), u2h_(hv.x));
            s = __hfma2(u2h_(w.y), u2h_(hv.y), s);
            s = __hfma2(u2h_(w.z), u2h_(hv.z), s);
            s = __hfma2(u2h_(w.w), u2h_(hv.w), s);
            float2 f = __half22float2(s);
            ull ff;
            asm("mov.b64 %0, {%1, %2};" : "=l"(ff) : "f"(f.x), "f"(f.y));
            asm("add.rn.f32x2 %0, %0, %1;" : "+l"(acc[r]) : "l"(ff));
        }
    }
    #pragma unroll
    for (int r = 0; r < 4; r++) {
        float lo, hi;
        asm("mov.b64 {%0, %1}, %2;" : "=f"(lo), "=f"(hi) : "l"(acc[r]));
        out[r] = lo + hi;
    }
}

// ---------------- persistent LSTM recurrence ----------------
__global__ __launch_bounds__(NTHR, 1) void lstm_rec() {
    extern __shared__ float smem[];
    __half* wc    = reinterpret_cast<__half*>(smem);         // NCACHE * HID halfs
    __half* h2_sh = wc + NCACHE * HID;                       // HID halfs
    float*  g_sh  = reinterpret_cast<float*>(h2_sh + HID);   // 64 gate pre-activations
    float*  c_sh  = g_sh + 64;                               // 16 cell states

    const int tid   = threadIdx.x;
    const int bid   = blockIdx.x;
    const int hbase = bid * HPB;

    // stage NCACHE weight rows into SMEM as fp16 (once)
    for (int idx = tid; idx < NCACHE * HID / 8; idx += NTHR) {
        const int lr  = idx >> 8;
        const int col = (idx & 255) * 8;
        const int gate = lr >> 4;
        const int hl   = lr & 15;
        const size_t row = (size_t)(gate * HID + hbase + hl);
        reinterpret_cast<uint4*>(wc + (size_t)lr * HID)[col / 8] =
            __ldg(reinterpret_cast<const uint4*>(g_whh + row * HID + col));
    }
    if (tid < HPB) c_sh[tid] = 0.0f;

    const int warp = tid >> 5;
    const int lane = tid & 31;
    const int lr0  = warp * 4;
    const int gate0 = lr0 >> 4;
    const int hl0   = lr0 & 15;
    const size_t rowg0 = (size_t)(gate0 * HID + hbase + hl0);
    const __half* sm_base = wc + (size_t)lr0 * HID;
    const __half* gl_base = g_whh + rowg0 * HID;
    const bool use_sm = (lr0 + 3 < NCACHE);

    // staging assignment: thread stages 4 floats of block (tid>>2)'s message line
    const int mb = tid >> 2;          // message line / producer block id, 0..127
    const int mq = tid & 3;           // float4 quarter within the 16 h values

    for (int t = 0; t < TLEN; t++) {
        // xg prefetch (h-independent; overlaps the wait below)
        float4 xgv = make_float4(0.f, 0.f, 0.f, 0.f);
        if (lane == 0)
            xgv = __ldg(reinterpret_cast<const float4*>(g_xg + (size_t)t * R4 + rowg0));

        // poll-and-stage: wait for line mb's tag >= t, then pull its h quarter
        {
            const Msg* ml = &g_msg[t & 1][mb];
            while (*(volatile const unsigned*)&ml->tag < (unsigned)t) { }
            __threadfence();                               // acquire
            float4 v = __ldcg(reinterpret_cast<const float4*>(ml->h + mq * 4));
            __half2 p0 = __floats2half2_rn(v.x, v.y);
            __half2 p1 = __floats2half2_rn(v.z, v.w);
            uint2 u;
            u.x = *reinterpret_cast<unsigned*>(&p0);
            u.y = *reinterpret_cast<unsigned*>(&p1);
            reinterpret_cast<uint2*>(h2_sh)[tid] = u;      // halves [tid*4 .. tid*4+3]
        }
        __syncthreads();                                    // h2_sh complete

        float a[4];
        if (use_sm) dot4<true >(sm_base, h2_sh, lane, a);
        else        dot4<false>(gl_base, h2_sh, lane, a);

        #pragma unroll
        for (int off = 16; off; off >>= 1) {
            a[0] += __shfl_xor_sync(0xFFFFFFFFu, a[0], off);
            a[1] += __shfl_xor_sync(0xFFFFFFFFu, a[1], off);
            a[2] += __shfl_xor_sync(0xFFFFFFFFu, a[2], off);
            a[3] += __shfl_xor_sync(0xFFFFFFFFu, a[3], off);
        }
        if (lane == 0) {
            g_sh[lr0 + 0] = a[0] + xgv.x;
            g_sh[lr0 + 1] = a[1] + xgv.y;
            g_sh[lr0 + 2] = a[2] + xgv.z;
            g_sh[lr0 + 3] = a[3] + xgv.w;
        }
        __syncthreads();                                    // g_sh complete

        // warp 0 only: activations + publish; other warps run ahead to next poll
        if (warp == 0) {
            if (tid < HPB) {
                const float iv = sigmoidf_(g_sh[tid]);
                const float fv = sigmoidf_(g_sh[16 + tid]);
                const float gv = tanhf(g_sh[32 + tid]);
                const float ov = sigmoidf_(g_sh[48 + tid]);
                const float c  = fv * c_sh[tid] + iv * gv;
                c_sh[tid] = c;
                g_msg[(t + 1) & 1][bid].h[tid] = ov * tanhf(c);
            }
            __syncwarp();
            if (lane == 0) {
                __threadfence();                            // release h stores
                *(volatile unsigned*)&g_msg[(t + 1) & 1][bid].tag = (unsigned)(t + 1);
            }
        }
        // no end-of-step block sync: next step's poll on own line (published by
        // warp 0) orders all consumers behind the publish.
    }
}

// ---------------- output layer ----------------
__global__ void out_kernel(const float* __restrict__ W_out,
                           const float* __restrict__ b_out,
                           float* __restrict__ out) {
    __shared__ float red[8];
    const int tid = threadIdx.x;   // 256 threads
    float s = 0.f;
    for (int j = tid; j < HID; j += 256) {
        // final h(TLEN) lives in msg buffer 0 (TLEN even)
        float hv = g_msg[0][j >> 4].h[j & 15];
        s += hv * W_out[j];
    }
    #pragma unroll
    for (int off = 16; off; off >>= 1) s += __shfl_xor_sync(0xFFFFFFFFu, s, off);
    if ((tid & 31) == 0) red[tid >> 5] = s;
    __syncthreads();
    if (tid < 8) {
        float v = red[tid];
        #pragma unroll
        for (int off = 4; off; off >>= 1) v += __shfl_xor_sync(0xFFu, v, off);
        if (tid == 0) out[0] = v + b_out[0];
    }
}

// ---------------- launch ----------------
extern "C" void kernel_launch(void* const* d_in, const int* in_sizes, int n_in,
                              void* d_out, int out_size) {
    const float* x     = (const float*)d_in[0];
    const float* W_ih  = (const float*)d_in[1];
    const float* W_hh  = (const float*)d_in[2];
    const float* b_ih  = (const float*)d_in[3];
    const float* b_hh  = (const float*)d_in[4];
    const float* W_out = (const float*)d_in[5];
    const float* b_out = (const float*)d_in[6];
    float* out = (float*)d_out;

    init_kernel<<<1, 256>>>();
    prep_whh<<<2048, 256>>>(W_hh);

    dim3 ggrid(R4 / GBN, TLEN / GBM);
    xg_gemm<<<ggrid, 256>>>(x, W_ih, b_ih, b_hh);

    cudaFuncSetAttribute(lstm_rec, cudaFuncAttributeMaxDynamicSharedMemorySize, REC_SMEM_BYTES);
    lstm_rec<<<NBLK, NTHR, REC_SMEM_BYTES>>>();

    out_kernel<<<1, 256>>>(W_out, b_out, out);
}

// round 8
// speedup vs baseline: 1.8142x; 1.3450x over previous
#include <cuda_runtime.h>
#include <cuda_fp16.h>
#include <math.h>
#include <stdint.h>

typedef unsigned long long ull;

// ---------------- problem constants ----------------
#define HID  2048
#define R4   8192          // 4 * HID
#define TLEN 4096
#define IDIM 1024

// ---------------- recurrence kernel config ----------------
#define NBLK   128
#define NTHR   512
#define HPB    16          // h indices per block (2048 / 128)
#define NCACHE 48          // rows of W_hh (fp16) cached in SMEM per block

// smem: 48 rows * 2048 halfs + h 2048 halfs + g 64 f + c 16 f
#define REC_SMEM_BYTES (NCACHE * HID * 2 + HID * 2 + (64 + 16) * 4)

// ---------------- scratch (device globals; no allocation) ----------------
__device__ float    g_xg[(size_t)TLEN * R4];      // precomputed input gates, 128 MB
__device__ __half   g_whh[(size_t)R4 * HID];      // fp16 copy of W_hh, 32 MB

// message line: 16 h values (fp32) + tag, one 128B line per block, double buffered
struct alignas(128) Msg { float h[16]; unsigned tag; unsigned pad[15]; };
__device__ Msg g_msg[2][NBLK];

// ---------------- acquire / release helpers ----------------
__device__ __forceinline__ unsigned ld_acq_(const unsigned* p) {
    unsigned v;
    asm volatile("ld.global.acquire.gpu.b32 %0, [%1];" : "=r"(v) : "l"(p) : "memory");
    return v;
}

// ---------------- init ----------------
__global__ void init_kernel() {
    unsigned* p = reinterpret_cast<unsigned*>(g_msg);
    for (int i = threadIdx.x; i < 2 * NBLK * 32; i += blockDim.x) p[i] = 0u;
}

// ---------------- W_hh fp32 -> fp16 ----------------
__global__ void prep_whh(const float* __restrict__ W_hh) {
    const size_t n2 = (size_t)R4 * HID / 2;
    const size_t stride = (size_t)gridDim.x * blockDim.x;
    for (size_t i = (size_t)blockIdx.x * blockDim.x + threadIdx.x; i < n2; i += stride) {
        float2 v = reinterpret_cast<const float2*>(W_hh)[i];
        reinterpret_cast<__half2*>(g_whh)[i] = __floats2half2_rn(v.x, v.y);
    }
}

// ---------------- xg GEMM: 128x128x16 tiles, 8x8 micro (proven) ----------------
#define GBM 128
#define GBN 128
#define GBK 16
#define GAP 132

__global__ __launch_bounds__(256) void xg_gemm(const float* __restrict__ x,
                                               const float* __restrict__ W_ih,
                                               const float* __restrict__ b_ih,
                                               const float* __restrict__ b_hh) {
    __shared__ float As[GBK * GAP];
    __shared__ float Bs[GBK * GAP];
    const int tid = threadIdx.x;
    const int tx = tid & 15;
    const int ty = tid >> 4;
    const int rt = blockIdx.x * GBN;
    const int tt = blockIdx.y * GBM;

    const int lr = tid >> 2;
    const int lc = (tid & 3) * 4;

    float acc[2][2][4][4];
    #pragma unroll
    for (int a = 0; a < 2; a++)
        #pragma unroll
        for (int b = 0; b < 2; b++)
            #pragma unroll
            for (int i = 0; i < 4; i++)
                #pragma unroll
                for (int j = 0; j < 4; j++) acc[a][b][i][j] = 0.f;

    for (int k0 = 0; k0 < IDIM; k0 += GBK) {
        float4 a0 = __ldg(reinterpret_cast<const float4*>(&x[(size_t)(tt + lr) * IDIM + k0 + lc]));
        float4 a1 = __ldg(reinterpret_cast<const float4*>(&x[(size_t)(tt + lr + 64) * IDIM + k0 + lc]));
        float4 w0 = __ldg(reinterpret_cast<const float4*>(&W_ih[(size_t)(rt + lr) * IDIM + k0 + lc]));
        float4 w1 = __ldg(reinterpret_cast<const float4*>(&W_ih[(size_t)(rt + lr + 64) * IDIM + k0 + lc]));

        As[(lc + 0) * GAP + lr] = a0.x; As[(lc + 1) * GAP + lr] = a0.y;
        As[(lc + 2) * GAP + lr] = a0.z; As[(lc + 3) * GAP + lr] = a0.w;
        As[(lc + 0) * GAP + lr + 64] = a1.x; As[(lc + 1) * GAP + lr + 64] = a1.y;
        As[(lc + 2) * GAP + lr + 64] = a1.z; As[(lc + 3) * GAP + lr + 64] = a1.w;

        Bs[(lc + 0) * GAP + lr] = w0.x; Bs[(lc + 1) * GAP + lr] = w0.y;
        Bs[(lc + 2) * GAP + lr] = w0.z; Bs[(lc + 3) * GAP + lr] = w0.w;
        Bs[(lc + 0) * GAP + lr + 64] = w1.x; Bs[(lc + 1) * GAP + lr + 64] = w1.y;
        Bs[(lc + 2) * GAP + lr + 64] = w1.z; Bs[(lc + 3) * GAP + lr + 64] = w1.w;

        __syncthreads();

        #pragma unroll
        for (int k = 0; k < GBK; k++) {
            float4 av0 = *reinterpret_cast<const float4*>(&As[k * GAP + ty * 4]);
            float4 av1 = *reinterpret_cast<const float4*>(&As[k * GAP + 64 + ty * 4]);
            float4 bv0 = *reinterpret_cast<const float4*>(&Bs[k * GAP + tx * 4]);
            float4 bv1 = *reinterpret_cast<const float4*>(&Bs[k * GAP + 64 + tx * 4]);
            float am[2][4] = {{av0.x, av0.y, av0.z, av0.w}, {av1.x, av1.y, av1.z, av1.w}};
            float bn[2][4] = {{bv0.x, bv0.y, bv0.z, bv0.w}, {bv1.x, bv1.y, bv1.z, bv1.w}};
            #pragma unroll
            for (int a = 0; a < 2; a++)
                #pragma unroll
                for (int i = 0; i < 4; i++)
                    #pragma unroll
                    for (int b = 0; b < 2; b++)
                        #pragma unroll
                        for (int j = 0; j < 4; j++)
                            acc[a][b][i][j] += am[a][i] * bn[b][j];
        }
        __syncthreads();
    }

    #pragma unroll
    for (int b = 0; b < 2; b++) {
        const int rbase = rt + b * 64 + tx * 4;
        float bias[4];
        #pragma unroll
        for (int j = 0; j < 4; j++) bias[j] = b_ih[rbase + j] + b_hh[rbase + j];
        #pragma unroll
        for (int a = 0; a < 2; a++) {
            #pragma unroll
            for (int i = 0; i < 4; i++) {
                const int t = tt + a * 64 + ty * 4 + i;
                float4 o;
                o.x = acc[a][b][i][0] + bias[0];
                o.y = acc[a][b][i][1] + bias[1];
                o.z = acc[a][b][i][2] + bias[2];
                o.w = acc[a][b][i][3] + bias[3];
                *reinterpret_cast<float4*>(&g_xg[(size_t)t * R4 + rbase]) = o;
            }
        }
    }
}

// fast sigmoid/tanh via HW EX2 path (~2 ulp on exp)
__device__ __forceinline__ float sigmoidf_(float v) { return 1.0f / (1.0f + __expf(-v)); }
__device__ __forceinline__ float tanhf_(float v)    { return 2.0f / (1.0f + __expf(-2.0f * v)) - 1.0f; }
__device__ __forceinline__ __half2 u2h_(unsigned u) { return *reinterpret_cast<__half2*>(&u); }

// ---------------- persistent LSTM recurrence ----------------
// Uniform warp work: each warp computes 3 SMEM-cached rows (local rows 3w..3w+2,
// gates i/f/g) + 1 L2-streamed row (local row 48+w, gate o).
__global__ __launch_bounds__(NTHR, 1) void lstm_rec() {
    extern __shared__ float smem[];
    __half* wc    = reinterpret_cast<__half*>(smem);         // NCACHE * HID halfs
    __half* h2_sh = wc + NCACHE * HID;                       // HID halfs
    float*  g_sh  = reinterpret_cast<float*>(h2_sh + HID);   // 64 gate pre-activations
    float*  c_sh  = g_sh + 64;                               // 16 cell states

    const int tid   = threadIdx.x;
    const int bid   = blockIdx.x;
    const int hbase = bid * HPB;

    // stage local rows 0..47 (gates i,f,g) into SMEM as fp16 (once)
    for (int idx = tid; idx < NCACHE * HID / 8; idx += NTHR) {
        const int lr  = idx >> 8;
        const int col = (idx & 255) * 8;
        const int gate = lr >> 4;
        const int hl   = lr & 15;
        const size_t row = (size_t)(gate * HID + hbase + hl);
        reinterpret_cast<uint4*>(wc + (size_t)lr * HID)[col / 8] =
            __ldg(reinterpret_cast<const uint4*>(g_whh + row * HID + col));
    }
    if (tid < HPB) c_sh[tid] = 0.0f;

    const int warp = tid >> 5;
    const int lane = tid & 31;

    // this warp's rows
    const __half* ws0 = wc + (size_t)(3 * warp + 0) * HID;   // smem rows
    const __half* ws1 = wc + (size_t)(3 * warp + 1) * HID;
    const __half* ws2 = wc + (size_t)(3 * warp + 2) * HID;
    const __half* wg  = g_whh + (size_t)(3 * HID + hbase + warp) * HID;  // o-gate row from L2

    // xg index for this lane's assigned local row (lanes 0..3)
    int my_lrow = (lane < 3) ? (3 * warp + lane) : (48 + warp);
    const size_t my_xg_row = (size_t)((my_lrow >> 4) * HID + hbase + (my_lrow & 15));

    // message staging: thread stages 4 floats of line (tid>>2)
    const int mb = tid >> 2;
    const int mq = tid & 3;

    for (int t = 0; t < TLEN; t++) {
        // xg prefetch (h-independent, overlaps the wait)
        float xgl = 0.f;
        if (lane < 4)
            xgl = __ldg(g_xg + (size_t)t * R4 + my_xg_row);

        // poll-and-stage: acquire-load tag, then pull h quarter (no fences)
        {
            const Msg* ml = &g_msg[t & 1][mb];
            while (ld_acq_(&ml->tag) < (unsigned)t) { }
            float4 v = __ldcg(reinterpret_cast<const float4*>(ml->h + mq * 4));
            __half2 p0 = __floats2half2_rn(v.x, v.y);
            __half2 p1 = __floats2half2_rn(v.z, v.w);
            uint2 u;
            u.x = *reinterpret_cast<unsigned*>(&p0);
            u.y = *reinterpret_cast<unsigned*>(&p1);
            reinterpret_cast<uint2*>(h2_sh)[tid] = u;
        }
        __syncthreads();                                    // h2_sh complete

        // 3 smem rows + 1 global row dot, HFMA2 chunks -> f32x2 accumulators
        ull acc0 = 0ull, acc1 = 0ull, acc2 = 0ull, acc3 = 0ull;
        #pragma unroll
        for (int ch = 0; ch < 8; ch++) {
            const int off = ch * 256 + lane * 8;   // half index
            uint4 w3 = __ldg(reinterpret_cast<const uint4*>(wg + off));   // L2 row first (latency)
            uint4 hv = *reinterpret_cast<const uint4*>(h2_sh + off);
            uint4 w0 = *reinterpret_cast<const uint4*>(ws0 + off);
            uint4 w1 = *reinterpret_cast<const uint4*>(ws1 + off);
            uint4 w2 = *reinterpret_cast<const uint4*>(ws2 + off);

            __half2 s0 = __hmul2(u2h_(w0.x), u2h_(hv.x));
            s0 = __hfma2(u2h_(w0.y), u2h_(hv.y), s0);
            s0 = __hfma2(u2h_(w0.z), u2h_(hv.z), s0);
            s0 = __hfma2(u2h_(w0.w), u2h_(hv.w), s0);
            __half2 s1 = __hmul2(u2h_(w1.x), u2h_(hv.x));
            s1 = __hfma2(u2h_(w1.y), u2h_(hv.y), s1);
            s1 = __hfma2(u2h_(w1.z), u2h_(hv.z), s1);
            s1 = __hfma2(u2h_(w1.w), u2h_(hv.w), s1);
            __half2 s2 = __hmul2(u2h_(w2.x), u2h_(hv.x));
            s2 = __hfma2(u2h_(w2.y), u2h_(hv.y), s2);
            s2 = __hfma2(u2h_(w2.z), u2h_(hv.z), s2);
            s2 = __hfma2(u2h_(w2.w), u2h_(hv.w), s2);
            __half2 s3 = __hmul2(u2h_(w3.x), u2h_(hv.x));
            s3 = __hfma2(u2h_(w3.y), u2h_(hv.y), s3);
            s3 = __hfma2(u2h_(w3.z), u2h_(hv.z), s3);
            s3 = __hfma2(u2h_(w3.w), u2h_(hv.w), s3);

            float2 f0 = __half22float2(s0);
            float2 f1 = __half22float2(s1);
            float2 f2 = __half22float2(s2);
            float2 f3 = __half22float2(s3);
            ull ff;
            asm("mov.b64 %0, {%1, %2};" : "=l"(ff) : "f"(f0.x), "f"(f0.y));
            asm("add.rn.f32x2 %0, %0, %1;" : "+l"(acc0) : "l"(ff));
            asm("mov.b64 %0, {%1, %2};" : "=l"(ff) : "f"(f1.x), "f"(f1.y));
            asm("add.rn.f32x2 %0, %0, %1;" : "+l"(acc1) : "l"(ff));
            asm("mov.b64 %0, {%1, %2};" : "=l"(ff) : "f"(f2.x), "f"(f2.y));
            asm("add.rn.f32x2 %0, %0, %1;" : "+l"(acc2) : "l"(ff));
            asm("mov.b64 %0, {%1, %2};" : "=l"(ff) : "f"(f3.x), "f"(f3.y));
            asm("add.rn.f32x2 %0, %0, %1;" : "+l"(acc3) : "l"(ff));
        }

        float a0, a1, a2, a3;
        {
            float lo, hi;
            asm("mov.b64 {%0, %1}, %2;" : "=f"(lo), "=f"(hi) : "l"(acc0)); a0 = lo + hi;
            asm("mov.b64 {%0, %1}, %2;" : "=f"(lo), "=f"(hi) : "l"(acc1)); a1 = lo + hi;
            asm("mov.b64 {%0, %1}, %2;" : "=f"(lo), "=f"(hi) : "l"(acc2)); a2 = lo + hi;
            asm("mov.b64 {%0, %1}, %2;" : "=f"(lo), "=f"(hi) : "l"(acc3)); a3 = lo + hi;
        }
        #pragma unroll
        for (int off = 16; off; off >>= 1) {
            a0 += __shfl_xor_sync(0xFFFFFFFFu, a0, off);
            a1 += __shfl_xor_sync(0xFFFFFFFFu, a1, off);
            a2 += __shfl_xor_sync(0xFFFFFFFFu, a2, off);
            a3 += __shfl_xor_sync(0xFFFFFFFFu, a3, off);
        }
        // bring lane-held xg values to lane 0 and write gate pre-activations
        const float x0 = __shfl_sync(0xFFFFFFFFu, xgl, 0);
        const float x1 = __shfl_sync(0xFFFFFFFFu, xgl, 1);
        const float x2 = __shfl_sync(0xFFFFFFFFu, xgl, 2);
        const float x3 = __shfl_sync(0xFFFFFFFFu, xgl, 3);
        if (lane == 0) {
            g_sh[3 * warp + 0] = a0 + x0;
            g_sh[3 * warp + 1] = a1 + x1;
            g_sh[3 * warp + 2] = a2 + x2;
            g_sh[48 + warp]    = a3 + x3;
        }
        __syncthreads();                                    // g_sh complete

        // warp 0: activations + publish; other warps run ahead to next poll
        if (warp == 0) {
            if (tid < HPB) {
                const float iv = sigmoidf_(g_sh[tid]);
                const float fv = sigmoidf_(g_sh[16 + tid]);
                const float gv = tanhf_(g_sh[32 + tid]);
                const float ov = sigmoidf_(g_sh[48 + tid]);
                const float c  = fv * c_sh[tid] + iv * gv;
                c_sh[tid] = c;
                g_msg[(t + 1) & 1][bid].h[tid] = ov * tanhf_(c);
            }
            __syncwarp();
            if (lane == 0) {
                __threadfence();                            // order h stores before tag
                *(volatile unsigned*)&g_msg[(t + 1) & 1][bid].tag = (unsigned)(t + 1);
            }
        }
    }
}

// ---------------- output layer ----------------
__global__ void out_kernel(const float* __restrict__ W_out,
                           const float* __restrict__ b_out,
                           float* __restrict__ out) {
    __shared__ float red[8];
    const int tid = threadIdx.x;   // 256 threads
    float s = 0.f;
    for (int j = tid; j < HID; j += 256) {
        float hv = g_msg[0][j >> 4].h[j & 15];   // final h (TLEN even -> buffer 0)
        s += hv * W_out[j];
    }
    #pragma unroll
    for (int off = 16; off; off >>= 1) s += __shfl_xor_sync(0xFFFFFFFFu, s, off);
    if ((tid & 31) == 0) red[tid >> 5] = s;
    __syncthreads();
    if (tid < 8) {
        float v = red[tid];
        #pragma unroll
        for (int off = 4; off; off >>= 1) v += __shfl_xor_sync(0xFFu, v, off);
        if (tid == 0) out[0] = v + b_out[0];
    }
}

// ---------------- launch ----------------
extern "C" void kernel_launch(void* const* d_in, const int* in_sizes, int n_in,
                              void* d_out, int out_size) {
    const float* x     = (const float*)d_in[0];
    const float* W_ih  = (const float*)d_in[1];
    const float* W_hh  = (const float*)d_in[2];
    const float* b_ih  = (const float*)d_in[3];
    const float* b_hh  = (const float*)d_in[4];
    const float* W_out = (const float*)d_in[5];
    const float* b_out = (const float*)d_in[6];
    float* out = (float*)d_out;

    init_kernel<<<1, 256>>>();
    prep_whh<<<2048, 256>>>(W_hh);

    dim3 ggrid(R4 / GBN, TLEN / GBM);
    xg_gemm<<<ggrid, 256>>>(x, W_ih, b_ih, b_hh);

    cudaFuncSetAttribute(lstm_rec, cudaFuncAttributeMaxDynamicSharedMemorySize, REC_SMEM_BYTES);
    lstm_rec<<<NBLK, NTHR, REC_SMEM_BYTES>>>();

    out_kernel<<<1, 256>>>(W_out, b_out, out);
}